// round 13
// baseline (speedup 1.0000x reference)
#include <cuda_runtime.h>

#define IMG 28
#define NU 96
#define SDIM (IMG * NU)            // 2688
#define NUNITS (NU * NU)           // 9216
#define ROWV4 (SDIM / 4)           // 672 float4s per row
#define NV4 ((SDIM * SDIM) / 4)    // 1806336 float4s per plane
#define SEGS (SDIM * NU)           // 258048 unit-segments (7 f4s each)
#define K1_GRID 1184               // 8 x 148: one wave at 8 CTAs/SM

__device__ float g_unit_map[NUNITS];   // static-zeroed; tail re-zeroes each replay
__device__ float g_fm[NUNITS];
__device__ float g_va[NUNITS];
__device__ unsigned g_ctr = 0;         // CTA completion ticket; tail resets

// --- scoped-atomic helpers: release/acquire WITHOUT __threadfence, so no
// --- CCTL.IVALL (L1 flush) is ever emitted (R7's fusion killer).
__device__ __forceinline__ void red_add_release(float* p, float v) {
    asm volatile("red.release.gpu.add.f32 [%0], %1;" :: "l"(p), "f"(v) : "memory");
}
__device__ __forceinline__ unsigned atom_inc_acqrel(unsigned* p) {
    unsigned old;
    asm volatile("atom.acq_rel.gpu.add.u32 %0, [%1], 1;" : "=r"(old) : "l"(p) : "memory");
    return old;
}
__device__ __forceinline__ float ld_acquire_f32(const float* p) {
    float v;
    asm volatile("ld.acquire.gpu.f32 %0, [%1];" : "=f"(v) : "l"(p) : "memory");
    return v;
}

// ---------------------------------------------------------------------------
// Kernel 1 (fused): unit_map sums + (last CTA) argmin + modifier maps.
// Body: flat streaming (coalesced 512B warp loads) + warp-segmented shuffle
// suffix-sum (deltas 1,2,4 cover segment length 7); segment-start lanes
// publish via red.release.gpu (distinct addresses, no-return, no L1 flush).
// Ticket: atom.acq_rel counts CTAs; the LAST CTA acquire-loads the 9216 unit
// sums, does first-occurrence argmin, computes the 96x96 fm/va maps
// analytically (cartesian_distances[i,j,bi,bj] == sqrt((i-bi)^2+(j-bj)^2)
// by construction), then re-zeroes unit_map + ticket for the next replay.
// Release(publish) -> acq_rel(ticket) -> acquire(read) forms the sync chain;
// x lives in smem so even incidental L1 invalidations are harmless.
// ---------------------------------------------------------------------------
__global__ __launch_bounds__(256, 8) void k_block_sums(
        const float* __restrict__ som,
        const float* __restrict__ rv,
        const float* __restrict__ x,
        const float* __restrict__ lr_map,
        const float* __restrict__ radius) {
    __shared__ float sm_x[IMG * IMG];            // 784 floats, 3.1 KB

    const int t = threadIdx.x;
    if (t < 196) ((float4*)sm_x)[t] = ((const float4*)x)[t];
    __syncthreads();

    // segment-aligned CTA partition: CTA c handles segments [s0, s1)
    const unsigned s0 = (unsigned)(((unsigned long long)blockIdx.x * SEGS) / K1_GRID);
    const unsigned s1 = (unsigned)(((unsigned long long)(blockIdx.x + 1) * SEGS) / K1_GRID);
    const unsigned p_end = s1 * 7;               // f4 range end (exclusive)
    const int lane = t & 31;

    for (unsigned wb = s0 * 7 + (unsigned)(t - lane); wb < p_end; wb += 256) {
        const unsigned p = wb + lane;            // this lane's global f4 index
        const bool active = (p < p_end);
        const unsigned r = p % 7;                // phase within unit-segment

        float v = 0.0f;
        if (active) {
            const unsigned row = p / ROWV4;      // global row 0..2687
            const unsigned a = row % IMG;        // row within 28x28 block
            const float4 s4 = ((const float4*)som)[p];
            const float4 r4 = ((const float4*)rv)[p];
            const float4 x4 = ((const float4*)sm_x)[a * 7 + r];
            float d0 = s4.x - x4.x;
            float d1 = s4.y - x4.y;
            float d2 = s4.z - x4.z;
            float d3 = s4.w - x4.w;
            v = __fdividef(d0 * d0, r4.x) + __fdividef(d1 * d1, r4.y)
              + __fdividef(d2 * d2, r4.z) + __fdividef(d3 * d3, r4.w);
        }

        // segmented suffix-sum: first lane of each segment(-part) gets the sum
#pragma unroll
        for (int d = 1; d <= 4; d <<= 1) {
            float o = __shfl_down_sync(0xFFFFFFFFu, v, d);
            if ((r + d < 7) && (lane + d < 32)) v += o;
        }

        if (active && (r == 0 || lane == 0)) {
            const unsigned seg = p / 7;          // = row*96 + j
            const unsigned row = seg / NU;
            const unsigned j = seg - row * NU;
            const unsigned i = row / IMG;
            red_add_release(&g_unit_map[i * NU + j], v);
        }
    }
    __syncthreads();

    // ---- ticket: identify the last CTA ----
    __shared__ unsigned s_rank;
    if (t == 0) s_rank = atom_inc_acqrel(&g_ctr);
    __syncthreads();
    if (s_rank != K1_GRID - 1) return;

    // ---- last-CTA tail: argmin + modifier maps ----
    __shared__ float vmin[256];
    __shared__ int   imin[256];
    {
        // contiguous 36-unit chunks, ascending, strict < => first occurrence
        float bv = 3.4028235e38f;
        int bidx = 0;
        const int u0 = t * 36;
        for (int m = 0; m < 36; m++) {
            float v = ld_acquire_f32(&g_unit_map[u0 + m]);
            if (v < bv) { bv = v; bidx = u0 + m; }
        }
        vmin[t] = bv;
        imin[t] = bidx;
    }
    __syncthreads();
#pragma unroll
    for (int s = 128; s > 0; s >>= 1) {
        if (t < s) {
            float ov = vmin[t + s];
            int   oi = imin[t + s];
            if (ov < vmin[t] || (ov == vmin[t] && oi < imin[t])) {
                vmin[t] = ov;
                imin[t] = oi;
            }
        }
        __syncthreads();
    }

    const int best = imin[0];
    const int bi = best / NU;
    const int bj = best % NU;
    const float rr  = radius[best];
    const float lrb = lr_map[best];
    const float dist_mod = 1.0f / (2.0f * rr * rr);
    const float constant = -logf(1e-8f / lrb) / dist_mod;

    for (int u = t; u < NUNITS; u += 256) {
        const int ii = u / NU;
        const int jj = u % NU;
        const float di = (float)(ii - bi);
        const float dj = (float)(jj - bj);
        const float d = sqrtf(di * di + dj * dj);
        float mask = (d > rr) ? 0.0f : 1.0f;
        float fm = mask * lr_map[u] * expf(-d * dist_mod);
        float alpha = (0.9f - 0.5f) + 1.0f / (1.0f + expf(-d / constant));
        alpha = alpha * mask + (1.0f - mask);
        alpha = fminf(fmaxf(alpha, 0.0f), 1.0f);
        g_fm[u] = fm;
        g_va[u] = alpha;
        g_unit_map[u] = 0.0f;                 // reset for next replay
    }
    if (t == 0) g_ctr = 0;                    // reset ticket for next replay
}

// ---------------------------------------------------------------------------
// Kernel 3: elementwise update. K3_BATCH=2 (~32 regs) -> 8 CTAs/SM.
// Streaming stores (__stcs) keep the never-re-read output from evicting
// som/rv in L2. out[0] = som_new, out[1] = var_new.
// ---------------------------------------------------------------------------
#define K3_BATCH 2
__global__ __launch_bounds__(256) void k_update(
        const float* __restrict__ som,
        const float* __restrict__ rv,
        const float* __restrict__ x,
        float* __restrict__ out) {
    const unsigned base = blockIdx.x * (256 * K3_BATCH) + threadIdx.x;

    unsigned idx[K3_BATCH];
    float4 s4[K3_BATCH], r4[K3_BATCH], x4[K3_BATCH];
    float fm[K3_BATCH], va[K3_BATCH];

#pragma unroll
    for (int k = 0; k < K3_BATCH; k++) {
        idx[k] = base + k * 256;
        s4[k] = *(const float4*)(som + (size_t)idx[k] * 4);
        r4[k] = *(const float4*)(rv + (size_t)idx[k] * 4);
    }
#pragma unroll
    for (int k = 0; k < K3_BATCH; k++) {
        const int row = idx[k] / ROWV4;
        const int c4  = idx[k] % ROWV4;
        const int col = c4 * 4;
        const int i = row / IMG;
        const int a = row % IMG;
        const int j = col / IMG;
        const int b = col % IMG;           // multiple of 4 (28 % 4 == 0)
        fm[k] = g_fm[i * NU + j];
        va[k] = g_va[i * NU + j];
        x4[k] = *(const float4*)(x + a * IMG + b);
    }

#pragma unroll
    for (int k = 0; k < K3_BATCH; k++) {
        float4 sn, vn;
#define DO_LANE(L)                                                   \
        {                                                            \
            float s_ = s4[k].L;                                      \
            float xv = x4[k].L;                                      \
            float snew = s_ + fm[k] * (xv - s_);                     \
            snew = fminf(fmaxf(snew, 0.0f), 1.0f);                   \
            float dd = xv - snew;                                    \
            sn.L = snew;                                             \
            vn.L = va[k] * r4[k].L + (1.0f - va[k]) * dd * dd;       \
        }
        DO_LANE(x) DO_LANE(y) DO_LANE(z) DO_LANE(w)
#undef DO_LANE
        __stcs((float4*)out + idx[k], sn);
        __stcs((float4*)out + idx[k] + NV4, vn);
    }
}

// ---------------------------------------------------------------------------
// Launch — TWO kernels.
// inputs: 0=som, 1=running_variance, 2=learning_rates, 3=radius,
//         4=cartesian_distances (unused; analytic), 5=x
// out = (2, 2688, 2688) float32
// ---------------------------------------------------------------------------
extern "C" void kernel_launch(void* const* d_in, const int* in_sizes, int n_in,
                              void* d_out, int out_size) {
    const float* som  = (const float*)d_in[0];
    const float* rv   = (const float*)d_in[1];
    const float* lr   = (const float*)d_in[2];
    const float* rad  = (const float*)d_in[3];
    const float* x    = (const float*)d_in[5];
    float* out = (float*)d_out;

    k_block_sums<<<K1_GRID, 256>>>(som, rv, x, lr, rad);
    k_update<<<NV4 / (256 * K3_BATCH), 256>>>(som, rv, x, out);
}

// round 14
// speedup vs baseline: 1.4955x; 1.4955x over previous
#include <cuda_runtime.h>

#define IMG 28
#define NU 96
#define SDIM (IMG * NU)            // 2688
#define NUNITS (NU * NU)           // 9216
#define ROWV4 (SDIM / 4)           // 672 float4s per row
#define NV4 ((SDIM * SDIM) / 4)    // 1806336 float4s per plane
#define SEGS (SDIM * NU)           // 258048 unit-segments (7 f4s each)
#define K1_GRID 888                // 6 x 148: exactly one wave

__device__ float g_unit_map[NUNITS];   // static-zeroed; k2 re-zeroes each replay
__device__ float g_fm[NUNITS];
__device__ float g_va[NUNITS];

// ---------------------------------------------------------------------------
// Kernel 1: unit_map[i][j] = sum over 28x28 block of (som - x)^2 / rv.
// R12-best body: flat streaming (coalesced 512B warp loads) + warp-segmented
// shuffle suffix-sum; segment-start lanes publish via plain atomicAdd.
// PDL: trigger at start so k2's grid is prelaunched (k2 parks on its own
// griddepsync until this grid completes).
// ---------------------------------------------------------------------------
__global__ __launch_bounds__(256) void k_block_sums(
        const float* __restrict__ som,
        const float* __restrict__ rv,
        const float* __restrict__ x) {
    cudaTriggerProgrammaticLaunchCompletion();

    __shared__ float sm_x[IMG * IMG];            // 784 floats, 3.1 KB
    const int t = threadIdx.x;
    if (t < 196) ((float4*)sm_x)[t] = ((const float4*)x)[t];
    __syncthreads();

    const unsigned s0 = (unsigned)(((unsigned long long)blockIdx.x * SEGS) / K1_GRID);
    const unsigned s1 = (unsigned)(((unsigned long long)(blockIdx.x + 1) * SEGS) / K1_GRID);
    const unsigned p_end = s1 * 7;
    const int lane = t & 31;

    for (unsigned wb = s0 * 7 + (unsigned)(t - lane); wb < p_end; wb += 256) {
        const unsigned p = wb + lane;
        const bool active = (p < p_end);
        const unsigned r = p % 7;

        float v = 0.0f;
        if (active) {
            const unsigned row = p / ROWV4;
            const unsigned a = row % IMG;
            const float4 s4 = ((const float4*)som)[p];
            const float4 r4 = ((const float4*)rv)[p];
            const float4 x4 = ((const float4*)sm_x)[a * 7 + r];
            float d0 = s4.x - x4.x;
            float d1 = s4.y - x4.y;
            float d2 = s4.z - x4.z;
            float d3 = s4.w - x4.w;
            v = __fdividef(d0 * d0, r4.x) + __fdividef(d1 * d1, r4.y)
              + __fdividef(d2 * d2, r4.z) + __fdividef(d3 * d3, r4.w);
        }

#pragma unroll
        for (int d = 1; d <= 4; d <<= 1) {
            float o = __shfl_down_sync(0xFFFFFFFFu, v, d);
            if ((r + d < 7) && (lane + d < 32)) v += o;
        }

        if (active && (r == 0 || lane == 0)) {
            const unsigned seg = p / 7;          // = row*96 + j
            const unsigned row = seg / NU;
            const unsigned j = seg - row * NU;
            const unsigned i = row / IMG;
            atomicAdd(&g_unit_map[i * NU + j], v);
        }
    }
}

// ---------------------------------------------------------------------------
// Kernel 2: single CTA. Trigger at start (k3's first wave prelaunches and
// issues its som/rv loads during this kernel), then grid-sync on k1, then
// argmin (first-occurrence tiebreak) + fm/va maps + unit_map re-zero.
// cartesian_distances[i,j,bi,bj] == sqrt((i-bi)^2 + (j-bj)^2) -> analytic.
// ---------------------------------------------------------------------------
__global__ void k_modifiers(const float* __restrict__ lr_map,
                            const float* __restrict__ radius) {
    cudaTriggerProgrammaticLaunchCompletion();
    cudaGridDependencySynchronize();             // wait for k1's unit sums

    const int t = threadIdx.x;  // 1024 threads
    __shared__ float vmin[1024];
    __shared__ int   imin[1024];

    float bv = 3.4028235e38f;
    int   bidx = 0;
    for (int u = t; u < NUNITS; u += 1024) {
        float v = g_unit_map[u];
        if (v < bv) { bv = v; bidx = u; }
    }
    vmin[t] = bv;
    imin[t] = bidx;
    __syncthreads();
#pragma unroll
    for (int s = 512; s > 0; s >>= 1) {
        if (t < s) {
            float ov = vmin[t + s];
            int   oi = imin[t + s];
            if (ov < vmin[t] || (ov == vmin[t] && oi < imin[t])) {
                vmin[t] = ov;
                imin[t] = oi;
            }
        }
        __syncthreads();
    }

    const int best = imin[0];
    const int bi = best / NU;
    const int bj = best % NU;
    const float r   = radius[best];
    const float lrb = lr_map[best];
    const float dist_mod = 1.0f / (2.0f * r * r);
    const float constant = -logf(1e-8f / lrb) / dist_mod;

    for (int u = t; u < NUNITS; u += 1024) {
        const int ii = u / NU;
        const int jj = u % NU;
        const float di = (float)(ii - bi);
        const float dj = (float)(jj - bj);
        const float d = sqrtf(di * di + dj * dj);
        float mask = (d > r) ? 0.0f : 1.0f;
        float fm = mask * lr_map[u] * expf(-d * dist_mod);
        float alpha = (0.9f - 0.5f) + 1.0f / (1.0f + expf(-d / constant));
        alpha = alpha * mask + (1.0f - mask);
        alpha = fminf(fmaxf(alpha, 0.0f), 1.0f);
        g_fm[u] = fm;
        g_va[u] = alpha;
        g_unit_map[u] = 0.0f;                 // reset for next replay
    }
}

// ---------------------------------------------------------------------------
// Kernel 3: elementwise update. PDL secondary of k2: launches while k2 runs,
// ISSUES its som/rv loads immediately (pure inputs, never written by k1/k2),
// then grid-syncs before reading g_fm/g_va. K3_BATCH=2 (~32 regs, 8 CTAs/SM);
// __stcs streaming stores. out[0] = som_new, out[1] = var_new.
// ---------------------------------------------------------------------------
#define K3_BATCH 2
__global__ __launch_bounds__(256) void k_update(
        const float* __restrict__ som,
        const float* __restrict__ rv,
        const float* __restrict__ x,
        float* __restrict__ out) {
    const unsigned base = blockIdx.x * (256 * K3_BATCH) + threadIdx.x;

    unsigned idx[K3_BATCH];
    float4 s4[K3_BATCH], r4[K3_BATCH], x4[K3_BATCH];
    float fm[K3_BATCH], va[K3_BATCH];

#pragma unroll
    for (int k = 0; k < K3_BATCH; k++) {
        idx[k] = base + k * 256;
        s4[k] = *(const float4*)(som + (size_t)idx[k] * 4);
        r4[k] = *(const float4*)(rv + (size_t)idx[k] * 4);
    }

    cudaGridDependencySynchronize();             // wait for k2's fm/va

#pragma unroll
    for (int k = 0; k < K3_BATCH; k++) {
        const int row = idx[k] / ROWV4;
        const int c4  = idx[k] % ROWV4;
        const int col = c4 * 4;
        const int i = row / IMG;
        const int a = row % IMG;
        const int j = col / IMG;
        const int b = col % IMG;           // multiple of 4 (28 % 4 == 0)
        fm[k] = g_fm[i * NU + j];
        va[k] = g_va[i * NU + j];
        x4[k] = *(const float4*)(x + a * IMG + b);
    }

#pragma unroll
    for (int k = 0; k < K3_BATCH; k++) {
        float4 sn, vn;
#define DO_LANE(L)                                                   \
        {                                                            \
            float s_ = s4[k].L;                                      \
            float xv = x4[k].L;                                      \
            float snew = s_ + fm[k] * (xv - s_);                     \
            snew = fminf(fmaxf(snew, 0.0f), 1.0f);                   \
            float dd = xv - snew;                                    \
            sn.L = snew;                                             \
            vn.L = va[k] * r4[k].L + (1.0f - va[k]) * dd * dd;       \
        }
        DO_LANE(x) DO_LANE(y) DO_LANE(z) DO_LANE(w)
#undef DO_LANE
        __stcs((float4*)out + idx[k], sn);
        __stcs((float4*)out + idx[k] + NV4, vn);
    }
}

// ---------------------------------------------------------------------------
// Launch: k1 normal; k2 and k3 as PDL secondaries (programmatic stream
// serialization) so each prelaunches during its predecessor and overlaps
// its setup/load phase. All on the capture (default) stream.
// inputs: 0=som, 1=running_variance, 2=learning_rates, 3=radius,
//         4=cartesian_distances (unused; analytic), 5=x
// ---------------------------------------------------------------------------
extern "C" void kernel_launch(void* const* d_in, const int* in_sizes, int n_in,
                              void* d_out, int out_size) {
    const float* som  = (const float*)d_in[0];
    const float* rv   = (const float*)d_in[1];
    const float* lr   = (const float*)d_in[2];
    const float* rad  = (const float*)d_in[3];
    const float* x    = (const float*)d_in[5];
    float* out = (float*)d_out;

    k_block_sums<<<K1_GRID, 256>>>(som, rv, x);

    cudaLaunchAttribute attrs[1];
    attrs[0].id = cudaLaunchAttributeProgrammaticStreamSerialization;
    attrs[0].val.programmaticStreamSerializationAllowed = 1;

    {
        cudaLaunchConfig_t cfg = {};
        cfg.gridDim = dim3(1);
        cfg.blockDim = dim3(1024);
        cfg.attrs = attrs;
        cfg.numAttrs = 1;
        cfg.stream = 0;
        cudaLaunchKernelEx(&cfg, k_modifiers, lr, rad);
    }
    {
        cudaLaunchConfig_t cfg = {};
        cfg.gridDim = dim3(NV4 / (256 * K3_BATCH));
        cfg.blockDim = dim3(256);
        cfg.attrs = attrs;
        cfg.numAttrs = 1;
        cfg.stream = 0;
        cudaLaunchKernelEx(&cfg, k_update, som, rv, x, out);
    }
}